// round 13
// baseline (speedup 1.0000x reference)
#include <cuda_runtime.h>
#include <cuda_bf16.h>

#define SIDE 9
#define STATE 81
#define NA 5
#define ROWLEN 405
#define H 32
#define RPB 256           // rows per block == threads
#define GROUP 8           // rows staged per phase-A iteration
#define THREADS 256

// ---------------------------------------------------------------------------
// Packed f32x2 helpers (sm_103a FFMA2)
// ---------------------------------------------------------------------------
__device__ __forceinline__ unsigned long long pack2(float x) {
    unsigned long long r;
    asm("mov.b64 %0, {%1, %1};" : "=l"(r) : "f"(x));
    return r;
}
__device__ __forceinline__ void ffma2(unsigned long long& d,
                                      unsigned long long a,
                                      unsigned long long b) {
    asm("fma.rn.f32x2 %0, %1, %2, %0;" : "+l"(d) : "l"(a), "l"(b));
}
__device__ __forceinline__ void unpack2(unsigned long long p, float& lo, float& hi) {
    asm("mov.b64 {%0, %1}, %2;" : "=f"(lo), "=f"(hi) : "l"(p));
}

// Dynamic smem layout (floats):
// [ s_nsc 256*81 | s_ac 8*405 | s_imm 256 | sW1 81*32 | sW2 32*32 | sW3 32 | sb3 1 ]
#define OFF_NSC 0
#define OFF_AC  (OFF_NSC + RPB * STATE)
#define OFF_IMM (OFF_AC + GROUP * ROWLEN)
#define OFF_W1  (OFF_IMM + RPB)
#define OFF_W2  (OFF_W1 + STATE * H)
#define OFF_W3  (OFF_W2 + H * H)
#define OFF_B3  (OFF_W3 + H)
#define SMEM_FLOATS (OFF_B3 + 1)

__global__ __launch_bounds__(THREADS) void vpn_fused(
    const float* __restrict__ obs,          // (B, 3*STATE)
    const float* __restrict__ acr_g,        // (B, STATE*NA)
    const float* __restrict__ W1,
    const float* __restrict__ W2,
    const float* __restrict__ W3,
    const float* __restrict__ b3,
    float* __restrict__ out,                // [sym(B), imm(B), ret(B), nsc(B*81)]
    int B)
{
    extern __shared__ float smem[];
    float* s_nsc = smem + OFF_NSC;
    float* s_ac  = smem + OFF_AC;
    float* s_imm = smem + OFF_IMM;
    float* sW1   = smem + OFF_W1;
    float* sW2   = smem + OFF_W2;
    float* sW3   = smem + OFF_W3;
    float* sb3   = smem + OFF_B3;

    const int tid  = threadIdx.x;
    const int wid  = tid >> 5;
    const int lane = tid & 31;
    const long long blockRow0 = (long long)blockIdx.x * RPB;

    // Stage weights once (visible after the first phase-A __syncthreads).
    for (int i = tid; i < STATE * H; i += THREADS) sW1[i] = W1[i];
    for (int i = tid; i < H * H; i += THREADS)     sW2[i] = W2[i];
    if (tid < H)  sW3[tid] = W3[tid];
    if (tid == 0) sb3[0] = b3[0];

    // ---------------- Phase A: 32 iterations of 8-row groups ----------------
    for (int q = 0; q < RPB / GROUP; q++) {
        const long long gRow0 = blockRow0 + (long long)q * GROUP;

        // Block-wide float4 stage of 8 contiguous ac rows (3240 floats).
        if (gRow0 + GROUP <= B) {
            const float4* __restrict__ src =
                reinterpret_cast<const float4*>(acr_g + gRow0 * ROWLEN);
            float4* __restrict__ dst = reinterpret_cast<float4*>(s_ac);
            #pragma unroll
            for (int i = tid; i < GROUP * ROWLEN / 4; i += THREADS)
                dst[i] = __ldg(&src[i]);
        } else {
            for (int i = tid; i < GROUP * ROWLEN; i += THREADS) {
                const long long g = gRow0 * ROWLEN + i;
                if (g < (long long)B * ROWLEN) s_ac[i] = acr_g[g];
            }
        }
        __syncthreads();

        // Warp w gathers row gRow0 + w (8 warps, 8 rows, fully parallel).
        const long long row = gRow0 + wid;
        if (row < B) {
            const float* __restrict__ sp  = s_ac + wid * ROWLEN;
            const float* __restrict__ dem = obs + row * (3 * STATE) + 2 * STATE;
            float* __restrict__ nout = out + 3LL * B + row * STATE;
            float* __restrict__ nrow = s_nsc + (q * GROUP + wid) * STATE;

            float imm = 0.0f;
            #pragma unroll
            for (int k = 0; k < 3; k++) {
                const int c = lane + 32 * k;
                if (c < STATE) {
                    const int rr  = c / SIDE;
                    const int col = c - rr * SIDE;
                    float v = sp[c * NA + 0];
                    if (rr == 0)        v += sp[c * NA + 1];
                    if (rr < SIDE - 1)  v += sp[(c + SIDE) * NA + 1];
                    if (rr == SIDE - 1) v += sp[c * NA + 2];
                    if (rr > 0)         v += sp[(c - SIDE) * NA + 2];
                    if (col == 0)       v += sp[c * NA + 3];
                    if (col < SIDE - 1) v += sp[(c + 1) * NA + 3];
                    if (col == SIDE-1)  v += sp[c * NA + 4];
                    if (col > 0)        v += sp[(c - 1) * NA + 4];

                    nrow[c] = v;                      // smem (for phase B)
                    nout[c] = v;                      // gmem output
                    imm += fminf(v, __ldg(&dem[c]));
                }
            }
            #pragma unroll
            for (int o = 16; o; o >>= 1)
                imm += __shfl_xor_sync(0xffffffffu, imm, o);
            if (lane == 0) {
                out[(long long)B + row] = imm;
                s_imm[q * GROUP + wid] = imm;
            }
        }
        __syncthreads();   // s_ac reads complete before next stage
    }

    // ---------------- Phase B: round-3 thread-per-row MLP -------------------
    const long long b = blockRow0 + tid;
    if (b >= B) return;

    const float* __restrict__ myn = s_nsc + tid * STATE;

    unsigned long long h1p[H / 2];
    #pragma unroll
    for (int j = 0; j < H / 2; j++) h1p[j] = 0ULL;

    #pragma unroll 3
    for (int d = 0; d < STATE; d++) {
        const unsigned long long vd = pack2(myn[d]);
        const ulonglong2* __restrict__ w1p =
            reinterpret_cast<const ulonglong2*>(&sW1[d * H]);
        #pragma unroll
        for (int q = 0; q < H / 4; q++) {
            ulonglong2 w = w1p[q];
            ffma2(h1p[q * 2 + 0], vd, w.x);
            ffma2(h1p[q * 2 + 1], vd, w.y);
        }
    }

    float h1[H];
    #pragma unroll
    for (int j = 0; j < H / 2; j++) {
        float lo, hi;
        unpack2(h1p[j], lo, hi);
        h1[2 * j + 0] = fmaxf(lo, 0.0f);
        h1[2 * j + 1] = fmaxf(hi, 0.0f);
    }

    unsigned long long h2p[H / 2];
    #pragma unroll
    for (int j = 0; j < H / 2; j++) h2p[j] = 0ULL;
    #pragma unroll
    for (int i = 0; i < H; i++) {
        const unsigned long long vi = pack2(h1[i]);
        const ulonglong2* __restrict__ w2p =
            reinterpret_cast<const ulonglong2*>(&sW2[i * H]);
        #pragma unroll
        for (int q = 0; q < H / 4; q++) {
            ulonglong2 w = w2p[q];
            ffma2(h2p[q * 2 + 0], vi, w.x);
            ffma2(h2p[q * 2 + 1], vi, w.y);
        }
    }

    float ret = sb3[0];
    #pragma unroll
    for (int j = 0; j < H / 2; j++) {
        float lo, hi;
        unpack2(h2p[j], lo, hi);
        ret = fmaf(fmaxf(lo, 0.0f), sW3[2 * j + 0], ret);
        ret = fmaf(fmaxf(hi, 0.0f), sW3[2 * j + 1], ret);
    }

    const float imm = s_imm[tid];
    out[b]                      = imm + ret;  // symbolic_val
    out[2LL * (long long)B + b] = ret;        // next_return
}

static const int FUSED_SMEM_BYTES = SMEM_FLOATS * (int)sizeof(float);

extern "C" void kernel_launch(void* const* d_in, const int* in_sizes, int n_in,
                              void* d_out, int out_size) {
    const float* obs = (const float*)d_in[0];
    const float* action_count = (const float*)d_in[1];
    const float* W1 = (const float*)d_in[2];
    const float* W2 = (const float*)d_in[3];
    const float* W3 = (const float*)d_in[4];
    const float* b3 = (const float*)d_in[5];
    float* out = (float*)d_out;

    const int B = in_sizes[0] / (3 * STATE);

    cudaFuncSetAttribute(vpn_fused, cudaFuncAttributeMaxDynamicSharedMemorySize,
                         FUSED_SMEM_BYTES);

    const int blocks = (B + RPB - 1) / RPB;
    vpn_fused<<<blocks, THREADS, FUSED_SMEM_BYTES>>>(obs, action_count,
                                                     W1, W2, W3, b3, out, B);
}

// round 14
// speedup vs baseline: 2.0565x; 2.0565x over previous
#include <cuda_runtime.h>
#include <cuda_bf16.h>

#define SIDE 9
#define STATE 81
#define NA 5
#define ROWLEN 405
#define H 32
#define WARPS_K1 8
#define RPW 2                 // rows per warp in K1
#define K2_THREADS 256
#define K2_ROWS 256

// ---------------------------------------------------------------------------
// K1 v3: warp handles 2 rows. All 26 stage-LDGs issued before the first
// gather (doubles memory-level parallelism per warp); gather/reduce tail
// amortized over 2 rows. Scalar LDG staging (proven; float4 regressed).
// ---------------------------------------------------------------------------
__global__ __launch_bounds__(32 * WARPS_K1) void k1_nsc_reward(
    const float* __restrict__ obs,          // (B, 3*STATE)
    const float* __restrict__ acr_g,        // (B, STATE*NA)
    float* __restrict__ out,                // [sym(B), imm(B), ret(B), nsc(B*81)]
    int B)
{
    __shared__ float s[WARPS_K1][RPW * 416];

    const int wid  = threadIdx.x >> 5;
    const int lane = threadIdx.x & 31;
    const long long row0 =
        ((long long)blockIdx.x * WARPS_K1 + wid) * RPW;
    if (row0 >= B) return;

    float* __restrict__ sp = s[wid];

    // Stage both rows: 26 independent LDGs in flight.
    #pragma unroll
    for (int r = 0; r < RPW; r++) {
        const long long row = row0 + r;
        if (row < B) {
            const float* __restrict__ acr = acr_g + row * ROWLEN;
            #pragma unroll
            for (int k = 0; k < 13; k++) {
                const int i = lane + 32 * k;
                if (i < ROWLEN) sp[r * 416 + i] = __ldg(&acr[i]);
            }
        }
    }
    __syncwarp();

    #pragma unroll
    for (int r = 0; r < RPW; r++) {
        const long long row = row0 + r;
        if (row >= B) break;

        const float* __restrict__ sr  = sp + r * 416;
        const float* __restrict__ dem = obs + row * (3 * STATE) + 2 * STATE;
        float* __restrict__ nout = out + 3LL * B + row * STATE;

        float imm = 0.0f;
        #pragma unroll
        for (int k = 0; k < 3; k++) {
            const int c = lane + 32 * k;
            if (c < STATE) {
                const int rr  = c / SIDE;
                const int col = c - rr * SIDE;
                float v = sr[c * NA + 0];
                if (rr == 0)        v += sr[c * NA + 1];
                if (rr < SIDE - 1)  v += sr[(c + SIDE) * NA + 1];
                if (rr == SIDE - 1) v += sr[c * NA + 2];
                if (rr > 0)         v += sr[(c - SIDE) * NA + 2];
                if (col == 0)       v += sr[c * NA + 3];
                if (col < SIDE - 1) v += sr[(c + 1) * NA + 3];
                if (col == SIDE-1)  v += sr[c * NA + 4];
                if (col > 0)        v += sr[(c - 1) * NA + 4];

                nout[c] = v;
                imm += fminf(v, __ldg(&dem[c]));
            }
        }

        #pragma unroll
        for (int o = 16; o; o >>= 1)
            imm += __shfl_xor_sync(0xffffffffu, imm, o);
        if (lane == 0) out[(long long)B + row] = imm;
    }
}

// ---------------------------------------------------------------------------
// Packed f32x2 helpers (sm_103a FFMA2)
// ---------------------------------------------------------------------------
__device__ __forceinline__ unsigned long long pack2(float x) {
    unsigned long long r;
    asm("mov.b64 %0, {%1, %1};" : "=l"(r) : "f"(x));
    return r;
}
__device__ __forceinline__ void ffma2(unsigned long long& d,
                                      unsigned long long a,
                                      unsigned long long b) {
    asm("fma.rn.f32x2 %0, %1, %2, %0;" : "+l"(d) : "l"(a), "l"(b));
}
__device__ __forceinline__ void unpack2(unsigned long long p, float& lo, float& hi) {
    asm("mov.b64 {%0, %1}, %2;" : "=f"(lo), "=f"(hi) : "l"(p));
}

// ---------------------------------------------------------------------------
// K2: round-3 exact (best measured). Thread-per-row, block-staged nsc,
// broadcast weight LDS, FFMA2.
// ---------------------------------------------------------------------------
__global__ __launch_bounds__(K2_THREADS) void k2_mlp(
    const float* __restrict__ W1,
    const float* __restrict__ W2,
    const float* __restrict__ W3,
    const float* __restrict__ b3,
    float* __restrict__ out,
    int B)
{
    extern __shared__ float smem[];
    float* s_nsc = smem;                          // K2_ROWS * STATE
    float* sW1   = s_nsc + K2_ROWS * STATE;       // STATE * H
    float* sW2   = sW1 + STATE * H;               // H * H
    float* sW3   = sW2 + H * H;                   // H
    float* sb3   = sW3 + H;                       // 1

    for (int i = threadIdx.x; i < STATE * H; i += blockDim.x) sW1[i] = W1[i];
    for (int i = threadIdx.x; i < H * H; i += blockDim.x)     sW2[i] = W2[i];
    if (threadIdx.x < H)  sW3[threadIdx.x] = W3[threadIdx.x];
    if (threadIdx.x == 0) sb3[0] = b3[0];

    const long long blockRow0 = (long long)blockIdx.x * K2_ROWS;
    const float* __restrict__ nsc_g = out + 3LL * B;

    if (blockRow0 + K2_ROWS <= B) {
        const float4* __restrict__ src =
            reinterpret_cast<const float4*>(nsc_g + blockRow0 * STATE);
        float4* __restrict__ dst = reinterpret_cast<float4*>(s_nsc);
        #pragma unroll 4
        for (int i = threadIdx.x; i < K2_ROWS * STATE / 4; i += K2_THREADS)
            dst[i] = __ldg(&src[i]);
    } else {
        for (int i = threadIdx.x; i < K2_ROWS * STATE; i += K2_THREADS) {
            const long long g = blockRow0 * STATE + i;
            if (g < (long long)B * STATE) s_nsc[i] = nsc_g[g];
        }
    }
    __syncthreads();

    const long long b = blockRow0 + threadIdx.x;
    if (b >= B) return;

    const float* __restrict__ myn = s_nsc + threadIdx.x * STATE;

    unsigned long long h1p[H / 2];
    #pragma unroll
    for (int j = 0; j < H / 2; j++) h1p[j] = 0ULL;

    #pragma unroll 3
    for (int d = 0; d < STATE; d++) {
        const unsigned long long vd = pack2(myn[d]);
        const ulonglong2* __restrict__ w1p =
            reinterpret_cast<const ulonglong2*>(&sW1[d * H]);
        #pragma unroll
        for (int q = 0; q < H / 4; q++) {
            ulonglong2 w = w1p[q];
            ffma2(h1p[q * 2 + 0], vd, w.x);
            ffma2(h1p[q * 2 + 1], vd, w.y);
        }
    }

    float h1[H];
    #pragma unroll
    for (int j = 0; j < H / 2; j++) {
        float lo, hi;
        unpack2(h1p[j], lo, hi);
        h1[2 * j + 0] = fmaxf(lo, 0.0f);
        h1[2 * j + 1] = fmaxf(hi, 0.0f);
    }

    unsigned long long h2p[H / 2];
    #pragma unroll
    for (int j = 0; j < H / 2; j++) h2p[j] = 0ULL;
    #pragma unroll
    for (int i = 0; i < H; i++) {
        const unsigned long long vi = pack2(h1[i]);
        const ulonglong2* __restrict__ w2p =
            reinterpret_cast<const ulonglong2*>(&sW2[i * H]);
        #pragma unroll
        for (int q = 0; q < H / 4; q++) {
            ulonglong2 w = w2p[q];
            ffma2(h2p[q * 2 + 0], vi, w.x);
            ffma2(h2p[q * 2 + 1], vi, w.y);
        }
    }

    float ret = sb3[0];
    #pragma unroll
    for (int j = 0; j < H / 2; j++) {
        float lo, hi;
        unpack2(h2p[j], lo, hi);
        ret = fmaf(fmaxf(lo, 0.0f), sW3[2 * j + 0], ret);
        ret = fmaf(fmaxf(hi, 0.0f), sW3[2 * j + 1], ret);
    }

    const float imm = out[(long long)B + b];
    out[b]                      = imm + ret;  // symbolic_val
    out[2LL * (long long)B + b] = ret;        // next_return
}

static const int K2_SMEM_BYTES =
    (K2_ROWS * STATE + STATE * H + H * H + H + 1) * (int)sizeof(float);

extern "C" void kernel_launch(void* const* d_in, const int* in_sizes, int n_in,
                              void* d_out, int out_size) {
    const float* obs = (const float*)d_in[0];
    const float* action_count = (const float*)d_in[1];
    const float* W1 = (const float*)d_in[2];
    const float* W2 = (const float*)d_in[3];
    const float* W3 = (const float*)d_in[4];
    const float* b3 = (const float*)d_in[5];
    float* out = (float*)d_out;

    const int B = in_sizes[0] / (3 * STATE);

    cudaFuncSetAttribute(k2_mlp, cudaFuncAttributeMaxDynamicSharedMemorySize,
                         K2_SMEM_BYTES);

    const int rowsPerBlock1 = WARPS_K1 * RPW;
    const int blocks1 = (B + rowsPerBlock1 - 1) / rowsPerBlock1;
    k1_nsc_reward<<<blocks1, 32 * WARPS_K1>>>(obs, action_count, out, B);

    const int blocks2 = (B + K2_ROWS - 1) / K2_ROWS;
    k2_mlp<<<blocks2, K2_THREADS, K2_SMEM_BYTES>>>(W1, W2, W3, b3, out, B);
}

// round 15
// speedup vs baseline: 2.1955x; 1.0676x over previous
#include <cuda_runtime.h>
#include <cuda_bf16.h>

#define SIDE 9
#define STATE 81
#define NA 5
#define H 32
#define WARPS_K1 8
#define MAX_B 131072

// nsc transposed scratch: [d][b]
__device__ float g_nscT[(size_t)STATE * MAX_B];

// ---------------------------------------------------------------------------
// K1: warp-per-row scatter + reward + transposed scratch write (R7 form,
// measured ~67us incl. transpose).
// ---------------------------------------------------------------------------
__global__ __launch_bounds__(32 * WARPS_K1) void k1_nsc_reward(
    const float* __restrict__ obs,          // (B, 3*STATE)
    const float* __restrict__ acr_g,        // (B, STATE*NA)
    float* __restrict__ out,                // [sym(B), imm(B), ret(B), nsc(B*81)]
    int B)
{
    __shared__ float s_ac[WARPS_K1][416];
    __shared__ float s_nsc[WARPS_K1 * STATE];

    const int tid  = threadIdx.x;
    const int wid  = tid >> 5;
    const int lane = tid & 31;
    const long long row0 = (long long)blockIdx.x * WARPS_K1;
    const long long row  = row0 + wid;

    if (row < B) {
        const float* __restrict__ acr = acr_g + row * (STATE * NA);
        float* __restrict__ sp = s_ac[wid];
        #pragma unroll
        for (int k = 0; k < 13; k++) {
            const int i = lane + 32 * k;
            if (i < STATE * NA) sp[i] = __ldg(&acr[i]);
        }
        __syncwarp();

        const float* __restrict__ dem = obs + row * (3 * STATE) + 2 * STATE;
        float* __restrict__ nout = out + 3LL * B + row * STATE;
        float* __restrict__ nrow = s_nsc + wid * STATE;

        float imm = 0.0f;
        #pragma unroll
        for (int k = 0; k < 3; k++) {
            const int c = lane + 32 * k;
            if (c < STATE) {
                const int r   = c / SIDE;
                const int col = c - r * SIDE;
                float v = sp[c * NA + 0];
                if (r == 0)        v += sp[c * NA + 1];
                if (r < SIDE - 1)  v += sp[(c + SIDE) * NA + 1];
                if (r == SIDE - 1) v += sp[c * NA + 2];
                if (r > 0)         v += sp[(c - SIDE) * NA + 2];
                if (col == 0)      v += sp[c * NA + 3];
                if (col < SIDE - 1)v += sp[(c + 1) * NA + 3];
                if (col == SIDE-1) v += sp[c * NA + 4];
                if (col > 0)       v += sp[(c - 1) * NA + 4];

                nout[c] = v;                      // gmem, coalesced
                nrow[c] = v;                      // smem
                imm += fminf(v, __ldg(&dem[c]));
            }
        }

        #pragma unroll
        for (int o = 16; o; o >>= 1) imm += __shfl_xor_sync(0xffffffffu, imm, o);
        if (lane == 0) out[(long long)B + row] = imm;
    }
    __syncthreads();

    // Transposed write: g_nscT[d*B + row0 + j] = s_nsc[j*81 + d]
    for (int i = tid; i < STATE * WARPS_K1; i += 32 * WARPS_K1) {
        const int d = i >> 3;
        const int j = i & 7;
        if (row0 + j < B)
            g_nscT[(long long)d * B + row0 + j] = s_nsc[j * STATE + d];
    }
}

// ---------------------------------------------------------------------------
// Packed f32x2 helpers (sm_103a FFMA2)
// ---------------------------------------------------------------------------
__device__ __forceinline__ unsigned long long pack2(float x) {
    unsigned long long r;
    asm("mov.b64 %0, {%1, %1};" : "=l"(r) : "f"(x));
    return r;
}
__device__ __forceinline__ void ffma2(unsigned long long& d,
                                      unsigned long long a,
                                      unsigned long long b) {
    asm("fma.rn.f32x2 %0, %1, %2, %0;" : "+l"(d) : "l"(a), "l"(b));
}
__device__ __forceinline__ void unpack2(unsigned long long p, float& lo, float& hi) {
    asm("mov.b64 {%0, %1}, %2;" : "=f"(lo), "=f"(hi) : "l"(p));
}

// ---------------------------------------------------------------------------
// K2: R7 dataflow (thread-per-row, coalesced transposed LDG, broadcast weight
// LDS) with the register peak broken by parking h1 in smem per-thread-column:
// s_h1[tid + 256*j], bank = tid%32 (conflict-free), same-thread STS->LDS so
// no sync needed. ~55 live regs -> launch_bounds(256,4) -> 32 warps/SM.
// ---------------------------------------------------------------------------
__global__ __launch_bounds__(256, 4) void k2_mlp(
    const float* __restrict__ W1,
    const float* __restrict__ W2,
    const float* __restrict__ W3,
    const float* __restrict__ b3,
    float* __restrict__ out,
    int B)
{
    __shared__ float sW1[STATE * H];   // 10.4 KB
    __shared__ float sW2[H * H];       //  4.0 KB
    __shared__ float sW3[H];
    __shared__ float sb3;
    __shared__ float s_h1[256 * H];    // 32 KB  (per-thread column layout)

    for (int i = threadIdx.x; i < STATE * H; i += 256) sW1[i] = W1[i];
    for (int i = threadIdx.x; i < H * H; i += 256)     sW2[i] = W2[i];
    if (threadIdx.x < H)  sW3[threadIdx.x] = W3[threadIdx.x];
    if (threadIdx.x == 0) sb3 = b3[0];
    __syncthreads();

    const int tid = threadIdx.x;
    const long long b = (long long)blockIdx.x * 256 + tid;
    const bool valid = (b < B);
    const long long bc = valid ? b : (long long)(B - 1);

    // Early coalesced load of imm (covered by the MLP latency below).
    const float imm = __ldg(&out[(long long)B + bc]);

    // ---- Layer 1: full 32 columns, 16 f32x2 accumulators ----
    unsigned long long h1p[H / 2];
    #pragma unroll
    for (int j = 0; j < H / 2; j++) h1p[j] = 0ULL;

    const float* __restrict__ np = g_nscT + bc;
    #pragma unroll 9
    for (int d = 0; d < STATE; d++) {
        const unsigned long long vd = pack2(__ldg(np + (long long)d * B));
        const ulonglong2* __restrict__ w1p =
            reinterpret_cast<const ulonglong2*>(&sW1[d * H]);
        #pragma unroll
        for (int q = 0; q < H / 4; q++) {
            ulonglong2 w = w1p[q];
            ffma2(h1p[q * 2 + 0], vd, w.x);
            ffma2(h1p[q * 2 + 1], vd, w.y);
        }
    }

    // ReLU -> park h1 in smem (per-thread column; same-thread roundtrip,
    // no synchronization required). Kills the h1[32] register array.
    #pragma unroll
    for (int j = 0; j < H / 2; j++) {
        float lo, hi;
        unpack2(h1p[j], lo, hi);
        s_h1[tid + 256 * (2 * j + 0)] = fmaxf(lo, 0.0f);
        s_h1[tid + 256 * (2 * j + 1)] = fmaxf(hi, 0.0f);
    }

    // ---- Layer 2: accumulators reuse the freed registers ----
    unsigned long long h2p[H / 2];
    #pragma unroll
    for (int j = 0; j < H / 2; j++) h2p[j] = 0ULL;
    #pragma unroll
    for (int i = 0; i < H; i++) {
        const unsigned long long vi = pack2(s_h1[tid + 256 * i]);
        const ulonglong2* __restrict__ w2p =
            reinterpret_cast<const ulonglong2*>(&sW2[i * H]);
        #pragma unroll
        for (int q = 0; q < H / 4; q++) {
            ulonglong2 w = w2p[q];
            ffma2(h2p[q * 2 + 0], vi, w.x);
            ffma2(h2p[q * 2 + 1], vi, w.y);
        }
    }

    // ---- Layer 3 ----
    float ret = sb3;
    #pragma unroll
    for (int j = 0; j < H / 2; j++) {
        float lo, hi;
        unpack2(h2p[j], lo, hi);
        ret = fmaf(fmaxf(lo, 0.0f), sW3[2 * j + 0], ret);
        ret = fmaf(fmaxf(hi, 0.0f), sW3[2 * j + 1], ret);
    }

    if (valid) {
        out[b]                      = imm + ret;  // symbolic_val
        out[2LL * (long long)B + b] = ret;        // next_return
    }
}

extern "C" void kernel_launch(void* const* d_in, const int* in_sizes, int n_in,
                              void* d_out, int out_size) {
    const float* obs = (const float*)d_in[0];
    const float* action_count = (const float*)d_in[1];
    const float* W1 = (const float*)d_in[2];
    const float* W2 = (const float*)d_in[3];
    const float* W3 = (const float*)d_in[4];
    const float* b3 = (const float*)d_in[5];
    float* out = (float*)d_out;

    const int B = in_sizes[0] / (3 * STATE);

    const int blocks1 = (B + WARPS_K1 - 1) / WARPS_K1;
    k1_nsc_reward<<<blocks1, 32 * WARPS_K1>>>(obs, action_count, out, B);

    const int blocks2 = (B + 255) / 256;
    k2_mlp<<<blocks2, 256>>>(W1, W2, W3, b3, out, B);
}

// round 16
// speedup vs baseline: 2.3635x; 1.0765x over previous
#include <cuda_runtime.h>
#include <cuda_bf16.h>

#define SIDE 9
#define STATE 81
#define NA 5
#define H 32
#define WARPS_K1 8
#define MAX_B 131072
#define K2T 256                 // K2 threads; block covers 2*K2T rows

// nsc transposed scratch: [d][b]
__device__ float g_nscT[(size_t)STATE * MAX_B];

// ---------------------------------------------------------------------------
// K1: warp-per-row scatter + reward + transposed scratch write (R7 form).
// ---------------------------------------------------------------------------
__global__ __launch_bounds__(32 * WARPS_K1) void k1_nsc_reward(
    const float* __restrict__ obs,
    const float* __restrict__ acr_g,
    float* __restrict__ out,
    int B)
{
    __shared__ float s_ac[WARPS_K1][416];
    __shared__ float s_nsc[WARPS_K1 * STATE];

    const int tid  = threadIdx.x;
    const int wid  = tid >> 5;
    const int lane = tid & 31;
    const long long row0 = (long long)blockIdx.x * WARPS_K1;
    const long long row  = row0 + wid;

    if (row < B) {
        const float* __restrict__ acr = acr_g + row * (STATE * NA);
        float* __restrict__ sp = s_ac[wid];
        #pragma unroll
        for (int k = 0; k < 13; k++) {
            const int i = lane + 32 * k;
            if (i < STATE * NA) sp[i] = __ldg(&acr[i]);
        }
        __syncwarp();

        const float* __restrict__ dem = obs + row * (3 * STATE) + 2 * STATE;
        float* __restrict__ nout = out + 3LL * B + row * STATE;
        float* __restrict__ nrow = s_nsc + wid * STATE;

        float imm = 0.0f;
        #pragma unroll
        for (int k = 0; k < 3; k++) {
            const int c = lane + 32 * k;
            if (c < STATE) {
                const int r   = c / SIDE;
                const int col = c - r * SIDE;
                float v = sp[c * NA + 0];
                if (r == 0)        v += sp[c * NA + 1];
                if (r < SIDE - 1)  v += sp[(c + SIDE) * NA + 1];
                if (r == SIDE - 1) v += sp[c * NA + 2];
                if (r > 0)         v += sp[(c - SIDE) * NA + 2];
                if (col == 0)      v += sp[c * NA + 3];
                if (col < SIDE - 1)v += sp[(c + 1) * NA + 3];
                if (col == SIDE-1) v += sp[c * NA + 4];
                if (col > 0)       v += sp[(c - 1) * NA + 4];

                nout[c] = v;
                nrow[c] = v;
                imm += fminf(v, __ldg(&dem[c]));
            }
        }

        #pragma unroll
        for (int o = 16; o; o >>= 1) imm += __shfl_xor_sync(0xffffffffu, imm, o);
        if (lane == 0) out[(long long)B + row] = imm;
    }
    __syncthreads();

    for (int i = tid; i < STATE * WARPS_K1; i += 32 * WARPS_K1) {
        const int d = i >> 3;
        const int j = i & 7;
        if (row0 + j < B)
            g_nscT[(long long)d * B + row0 + j] = s_nsc[j * STATE + d];
    }
}

// ---------------------------------------------------------------------------
// Packed f32x2 helpers
// ---------------------------------------------------------------------------
__device__ __forceinline__ unsigned long long pack2(float x) {
    unsigned long long r;
    asm("mov.b64 %0, {%1, %1};" : "=l"(r) : "f"(x));
    return r;
}
__device__ __forceinline__ void ffma2(unsigned long long& d,
                                      unsigned long long a,
                                      unsigned long long b) {
    asm("fma.rn.f32x2 %0, %1, %2, %0;" : "+l"(d) : "l"(a), "l"(b));
}
__device__ __forceinline__ void unpack2(unsigned long long p, float& lo, float& hi) {
    asm("mov.b64 {%0, %1}, %2;" : "=f"(lo), "=f"(hi) : "l"(p));
}

// ---------------------------------------------------------------------------
// K2: 2 rows per thread (64 rows/warp share every weight wavefront), layer
// split into two 16-column passes (16 u64 accums), full h1 parked in smem
// per-thread-column (bank = tid%32, same-thread, no sync). nsc streamed
// coalesced from transposed scratch; pass-2 re-reads are L1-hot.
// ---------------------------------------------------------------------------
__global__ __launch_bounds__(K2T) void k2_mlp(
    const float* __restrict__ W1,
    const float* __restrict__ W2,
    const float* __restrict__ W3,
    const float* __restrict__ b3,
    float* __restrict__ out,
    int B)
{
    extern __shared__ float smem[];
    float* s_h1 = smem;                       // 2 rows * 32 cols * K2T
    float* sW1  = s_h1 + 2 * H * K2T;         // STATE*H
    float* sW2  = sW1 + STATE * H;            // H*H
    float* sW3  = sW2 + H * H;                // H
    float* sb3  = sW3 + H;                    // 1

    const int tid = threadIdx.x;
    for (int i = tid; i < STATE * H; i += K2T) sW1[i] = W1[i];
    for (int i = tid; i < H * H; i += K2T)     sW2[i] = W2[i];
    if (tid < H)  sW3[tid] = W3[tid];
    if (tid == 0) sb3[0] = b3[0];
    __syncthreads();

    const long long base = (long long)blockIdx.x * (2 * K2T);
    const long long b0 = base + tid;
    const long long b1 = base + K2T + tid;
    const bool ok0 = (b0 < B), ok1 = (b1 < B);
    const long long c0 = ok0 ? b0 : (long long)(B - 1);
    const long long c1 = ok1 ? b1 : (long long)(B - 1);

    const float imm0 = __ldg(&out[(long long)B + c0]);
    const float imm1 = __ldg(&out[(long long)B + c1]);

    // ---- Layer 1: two passes of 16 columns over both rows ----
    #pragma unroll
    for (int p = 0; p < 2; p++) {
        const int cb = 16 * p;
        unsigned long long a[16];
        #pragma unroll
        for (int j = 0; j < 16; j++) a[j] = 0ULL;

        #pragma unroll 9
        for (int d = 0; d < STATE; d++) {
            const unsigned long long va =
                pack2(__ldg(&g_nscT[(long long)d * B + c0]));
            const unsigned long long vb =
                pack2(__ldg(&g_nscT[(long long)d * B + c1]));
            const ulonglong2* __restrict__ wp =
                reinterpret_cast<const ulonglong2*>(&sW1[d * H + cb]);
            const ulonglong2 w0 = wp[0], w1 = wp[1], w2 = wp[2], w3 = wp[3];
            ffma2(a[0], va, w0.x); ffma2(a[1], va, w0.y);
            ffma2(a[2], va, w1.x); ffma2(a[3], va, w1.y);
            ffma2(a[4], va, w2.x); ffma2(a[5], va, w2.y);
            ffma2(a[6], va, w3.x); ffma2(a[7], va, w3.y);
            ffma2(a[8],  vb, w0.x); ffma2(a[9],  vb, w0.y);
            ffma2(a[10], vb, w1.x); ffma2(a[11], vb, w1.y);
            ffma2(a[12], vb, w2.x); ffma2(a[13], vb, w2.y);
            ffma2(a[14], vb, w3.x); ffma2(a[15], vb, w3.y);
        }

        // ReLU + park (per-thread column: bank = tid%32, no sync needed).
        #pragma unroll
        for (int j = 0; j < 8; j++) {
            float lo, hi;
            unpack2(a[j], lo, hi);
            s_h1[(0 * H + cb + 2 * j + 0) * K2T + tid] = fmaxf(lo, 0.0f);
            s_h1[(0 * H + cb + 2 * j + 1) * K2T + tid] = fmaxf(hi, 0.0f);
            unpack2(a[8 + j], lo, hi);
            s_h1[(1 * H + cb + 2 * j + 0) * K2T + tid] = fmaxf(lo, 0.0f);
            s_h1[(1 * H + cb + 2 * j + 1) * K2T + tid] = fmaxf(hi, 0.0f);
        }
    }

    // ---- Layer 2 + head: two passes of 16 columns over both rows ----
    float ret0 = sb3[0], ret1 = sb3[0];
    #pragma unroll
    for (int q = 0; q < 2; q++) {
        const int cb = 16 * q;
        unsigned long long z[16];
        #pragma unroll
        for (int j = 0; j < 16; j++) z[j] = 0ULL;

        #pragma unroll
        for (int i = 0; i < H; i++) {
            const unsigned long long va = pack2(s_h1[(0 * H + i) * K2T + tid]);
            const unsigned long long vb = pack2(s_h1[(1 * H + i) * K2T + tid]);
            const ulonglong2* __restrict__ wp =
                reinterpret_cast<const ulonglong2*>(&sW2[i * H + cb]);
            const ulonglong2 w0 = wp[0], w1 = wp[1], w2 = wp[2], w3 = wp[3];
            ffma2(z[0], va, w0.x); ffma2(z[1], va, w0.y);
            ffma2(z[2], va, w1.x); ffma2(z[3], va, w1.y);
            ffma2(z[4], va, w2.x); ffma2(z[5], va, w2.y);
            ffma2(z[6], va, w3.x); ffma2(z[7], va, w3.y);
            ffma2(z[8],  vb, w0.x); ffma2(z[9],  vb, w0.y);
            ffma2(z[10], vb, w1.x); ffma2(z[11], vb, w1.y);
            ffma2(z[12], vb, w2.x); ffma2(z[13], vb, w2.y);
            ffma2(z[14], vb, w3.x); ffma2(z[15], vb, w3.y);
        }

        const float* __restrict__ w3p = &sW3[cb];
        #pragma unroll
        for (int j = 0; j < 8; j++) {
            float lo, hi;
            unpack2(z[j], lo, hi);
            ret0 += fmaxf(lo, 0.0f) * w3p[2 * j] + fmaxf(hi, 0.0f) * w3p[2 * j + 1];
            unpack2(z[8 + j], lo, hi);
            ret1 += fmaxf(lo, 0.0f) * w3p[2 * j] + fmaxf(hi, 0.0f) * w3p[2 * j + 1];
        }
    }

    if (ok0) {
        out[b0]                      = imm0 + ret0;
        out[2LL * (long long)B + b0] = ret0;
    }
    if (ok1) {
        out[b1]                      = imm1 + ret1;
        out[2LL * (long long)B + b1] = ret1;
    }
}

static const int K2_SMEM_BYTES =
    (2 * H * K2T + STATE * H + H * H + H + 1) * (int)sizeof(float);

extern "C" void kernel_launch(void* const* d_in, const int* in_sizes, int n_in,
                              void* d_out, int out_size) {
    const float* obs = (const float*)d_in[0];
    const float* action_count = (const float*)d_in[1];
    const float* W1 = (const float*)d_in[2];
    const float* W2 = (const float*)d_in[3];
    const float* W3 = (const float*)d_in[4];
    const float* b3 = (const float*)d_in[5];
    float* out = (float*)d_out;

    const int B = in_sizes[0] / (3 * STATE);

    cudaFuncSetAttribute(k2_mlp, cudaFuncAttributeMaxDynamicSharedMemorySize,
                         K2_SMEM_BYTES);

    const int blocks1 = (B + WARPS_K1 - 1) / WARPS_K1;
    k1_nsc_reward<<<blocks1, 32 * WARPS_K1>>>(obs, action_count, out, B);

    const int rows2 = 2 * K2T;
    const int blocks2 = (B + rows2 - 1) / rows2;
    k2_mlp<<<blocks2, K2T, K2_SMEM_BYTES>>>(W1, W2, W3, b3, out, B);
}